// round 12
// baseline (speedup 1.0000x reference)
#include <cuda_runtime.h>
#include <cuda_fp16.h>
#include <cstdint>

// out[b,n] = sum_{c,hw} x[b,c,hw] * W_s[n,hw] * W_d[n,c] + W_b[n]
// GEMM D[(b,c),n] = x . Ws^T via fp16 mma.sync m16n8k16 (fp32 accum) — at the
// mma.sync issue-rate floor (~186us). Ws pre-converted fp16 + out pre-set to W_b
// in ONE merged prep kernel (MLP=4). Fused Wd epilogue via atomics.
// BM=BN=128, 256 thr, 2 CTAs/SM. BK=32, 3 stages. Split-K {800,800,800,736}.

#define M_DIM 8192
#define N_DIM 1024
#define K_DIM 3136
#define BM 128
#define BN 128
#define STAGES 3
#define A_ROW_B 160                    // 32 floats + 32B pad -> conflict-free LDS.64
#define B_ROW_B 80                     // 32 halfs + 16B pad  -> conflict-free ldmatrix
#define A_ST_BYTES (128 * A_ROW_B)     // 20480
#define B_ST_BYTES (128 * B_ROW_B)     // 10240
#define ST_BYTES   (A_ST_BYTES + B_ST_BYTES)   // 30720
#define SMEM_BYTES (STAGES * ST_BYTES)         // 92160 (x2 CTA = 180KB/SM)

__device__ __align__(16) __half g_Bh[(size_t)N_DIM * K_DIM];  // 6.4 MB fp16 Ws

__device__ __forceinline__ void cp_async16(void* s, const void* g) {
    uint32_t sa = (uint32_t)__cvta_generic_to_shared(s);
    asm volatile("cp.async.cg.shared.global [%0], [%1], 16;\n" :: "r"(sa), "l"(g));
}
__device__ __forceinline__ uint32_t pack_h2(float lo, float hi) {
    __half2 h = __floats2half2_rn(lo, hi);
    return *reinterpret_cast<uint32_t*>(&h);
}

// ---------------- merged prep: Ws->fp16 (MLP=4) + out=W_b ----------------
__global__ __launch_bounds__(256)
void prep_all(const float* __restrict__ Ws, const float* __restrict__ Wb,
              float* __restrict__ out) {
    const int bid = blockIdx.x;
    const int tid = threadIdx.x;
    if (bid < 784) {
        // convert 802816 float4s of Ws; 4 per thread, batched for MLP=4
        const size_t base = (size_t)bid * 1024 + tid;
        float4 v[4];
        #pragma unroll
        for (int j = 0; j < 4; j++)
            v[j] = reinterpret_cast<const float4*>(Ws)[base + j * 256];
        #pragma unroll
        for (int j = 0; j < 4; j++) {
            uint2 o;
            o.x = pack_h2(v[j].x, v[j].y);
            o.y = pack_h2(v[j].z, v[j].w);
            reinterpret_cast<uint2*>(g_Bh)[base + j * 256] = o;
        }
    } else {
        // init out (32768 floats) with broadcast bias: 4 blocks x 256 thr x 8 float4
        const int idx = (bid - 784) * 256 + tid;      // 0..1023
        const int n0 = (idx * 32) & (N_DIM - 1);
        float4 w[8];
        #pragma unroll
        for (int j = 0; j < 8; j++)
            w[j] = reinterpret_cast<const float4*>(Wb)[(n0 >> 2) + j];
        #pragma unroll
        for (int j = 0; j < 8; j++)
            reinterpret_cast<float4*>(out)[idx * 8 + j] = w[j];
    }
}

// ---------------- fused GEMM ----------------
__global__ __launch_bounds__(256, 2)
void gemm_fused(const float* __restrict__ A,
                const float* __restrict__ Wd, float* __restrict__ out) {
    extern __shared__ char smem[];

    const int tid  = threadIdx.x;
    const int warp = tid >> 5;      // 0..7
    const int lane = tid & 31;
    const int wm   = warp & 3;      // 4 warps along M (32 rows)
    const int wn   = warp >> 2;     // 2 warps along N (64 cols)
    const int g    = lane >> 2;
    const int t4   = lane & 3;

    const int gx = blockIdx.x;      // 0..7  N tile
    const int gy = blockIdx.y;      // 0..63 M tile
    const int sp = blockIdx.z;      // 0..3  K split
    const int b  = gy >> 1;
    const int c0 = (gy & 1) * BM;

    const int kst  = sp * 800;
    const int NT32 = (sp == 3) ? 23 : 25;

    const int arow = tid >> 3, acol = (tid & 7) * 16;   // +32*i rows
    const int brow = tid >> 2, bcol = (tid & 3) * 16;   // +64*i rows
    const float*  apt = A + (size_t)(gy * BM + arow) * K_DIM + kst + (acol >> 2);
    const __half* bpt = g_Bh + (size_t)(gx * BN + brow) * K_DIM + kst + (bcol >> 1);

    const int lm_row  = ((lane >> 4) & 1) * 8 + (lane & 7);
    const int lm_half = ((lane >> 3) & 1) * 8;

    float acc[2][8][4];
    #pragma unroll
    for (int i = 0; i < 2; i++)
        #pragma unroll
        for (int j = 0; j < 8; j++)
            #pragma unroll
            for (int k = 0; k < 4; k++) acc[i][j][k] = 0.f;

    auto load_stage = [&](int s, int kt) {
        char* st = smem + s * ST_BYTES;
        #pragma unroll
        for (int i = 0; i < 4; i++)
            cp_async16(st + (arow + 32 * i) * A_ROW_B + acol,
                       apt + (size_t)32 * i * K_DIM + kt * 32);
        #pragma unroll
        for (int i = 0; i < 2; i++)
            cp_async16(st + A_ST_BYTES + (brow + 64 * i) * B_ROW_B + bcol,
                       bpt + (size_t)64 * i * K_DIM + kt * 32);
    };

    load_stage(0, 0);
    asm volatile("cp.async.commit_group;\n" ::: "memory");
    load_stage(1, 1);
    asm volatile("cp.async.commit_group;\n" ::: "memory");

    const int aoff = (wm * 32 + g) * A_ROW_B + t4 * 8;

    int s_cur = 0, s_load = 2;
    #pragma unroll 1
    for (int kt = 0; kt < NT32; ++kt) {
        asm volatile("cp.async.wait_group 1;\n" ::: "memory");
        __syncthreads();

        if (kt + 2 < NT32) load_stage(s_load, kt + 2);
        asm volatile("cp.async.commit_group;\n" ::: "memory");

        const char* st  = smem + s_cur * ST_BYTES;
        const char* Asb = st + aoff;
        const uint32_t smB = (uint32_t)__cvta_generic_to_shared(st + A_ST_BYTES);

        uint32_t af0[2][4], af1[2][4], bf0[8][2], bf1[8][2];

        // ---- h0 B frags ----
        #pragma unroll
        for (int np = 0; np < 4; np++) {
            uint32_t addr = smB + ((wn * 64 + np * 16 + lm_row) * B_ROW_B) + (lm_half * 2);
            asm volatile(
                "ldmatrix.sync.aligned.m8n8.x4.shared.b16 {%0,%1,%2,%3}, [%4];\n"
                : "=r"(bf0[2 * np][0]), "=r"(bf0[2 * np][1]),
                  "=r"(bf0[2 * np + 1][0]), "=r"(bf0[2 * np + 1][1])
                : "r"(addr));
        }
        // ---- h0 A frags ----
        #pragma unroll
        for (int mi = 0; mi < 2; mi++) {
            const char* p = Asb + mi * 16 * A_ROW_B;
            float2 v0 = *(const float2*)(p);
            float2 v1 = *(const float2*)(p + 8 * A_ROW_B);
            float2 v2 = *(const float2*)(p + 32);
            float2 v3 = *(const float2*)(p + 8 * A_ROW_B + 32);
            af0[mi][0] = pack_h2(v0.x, v0.y);
            af0[mi][1] = pack_h2(v1.x, v1.y);
            af0[mi][2] = pack_h2(v2.x, v2.y);
            af0[mi][3] = pack_h2(v3.x, v3.y);
        }
        // ---- h1 B frags before h0 MMAs (keeps tensor pipe fed) ----
        #pragma unroll
        for (int np = 0; np < 4; np++) {
            uint32_t addr = smB + ((wn * 64 + np * 16 + lm_row) * B_ROW_B) + ((16 + lm_half) * 2);
            asm volatile(
                "ldmatrix.sync.aligned.m8n8.x4.shared.b16 {%0,%1,%2,%3}, [%4];\n"
                : "=r"(bf1[2 * np][0]), "=r"(bf1[2 * np][1]),
                  "=r"(bf1[2 * np + 1][0]), "=r"(bf1[2 * np + 1][1])
                : "r"(addr));
        }
        // ---- h0 MMAs ----
        #pragma unroll
        for (int mi = 0; mi < 2; mi++)
            #pragma unroll
            for (int ni = 0; ni < 8; ni++) {
                asm volatile(
                    "mma.sync.aligned.m16n8k16.row.col.f32.f16.f16.f32 "
                    "{%0,%1,%2,%3}, {%4,%5,%6,%7}, {%8,%9}, {%0,%1,%2,%3};\n"
                    : "+f"(acc[mi][ni][0]), "+f"(acc[mi][ni][1]),
                      "+f"(acc[mi][ni][2]), "+f"(acc[mi][ni][3])
                    : "r"(af0[mi][0]), "r"(af0[mi][1]), "r"(af0[mi][2]), "r"(af0[mi][3]),
                      "r"(bf0[ni][0]), "r"(bf0[ni][1]));
            }
        // ---- h1 A frags ----
        #pragma unroll
        for (int mi = 0; mi < 2; mi++) {
            const char* p = Asb + mi * 16 * A_ROW_B + 64;
            float2 v0 = *(const float2*)(p);
            float2 v1 = *(const float2*)(p + 8 * A_ROW_B);
            float2 v2 = *(const float2*)(p + 32);
            float2 v3 = *(const float2*)(p + 8 * A_ROW_B + 32);
            af1[mi][0] = pack_h2(v0.x, v0.y);
            af1[mi][1] = pack_h2(v1.x, v1.y);
            af1[mi][2] = pack_h2(v2.x, v2.y);
            af1[mi][3] = pack_h2(v3.x, v3.y);
        }
        // ---- h1 MMAs ----
        #pragma unroll
        for (int mi = 0; mi < 2; mi++)
            #pragma unroll
            for (int ni = 0; ni < 8; ni++) {
                asm volatile(
                    "mma.sync.aligned.m16n8k16.row.col.f32.f16.f16.f32 "
                    "{%0,%1,%2,%3}, {%4,%5,%6,%7}, {%8,%9}, {%0,%1,%2,%3};\n"
                    : "+f"(acc[mi][ni][0]), "+f"(acc[mi][ni][1]),
                      "+f"(acc[mi][ni][2]), "+f"(acc[mi][ni][3])
                    : "r"(af1[mi][0]), "r"(af1[mi][1]), "r"(af1[mi][2]), "r"(af1[mi][3]),
                      "r"(bf1[ni][0]), "r"(bf1[ni][1]));
            }

        s_cur  = (s_cur  == STAGES - 1) ? 0 : s_cur + 1;
        s_load = (s_load == STAGES - 1) ? 0 : s_load + 1;
    }

    // ---------------- fused epilogue ----------------
    #pragma unroll
    for (int ni = 0; ni < 8; ni++) {
        #pragma unroll
        for (int p = 0; p < 2; p++) {
            const int n = gx * BN + wn * 64 + ni * 8 + t4 * 2 + p;
            const float* wdp = Wd + (size_t)n * 256 + c0 + wm * 32 + g;
            float s = 0.f;
            #pragma unroll
            for (int mi = 0; mi < 2; mi++) {
                s += acc[mi][ni][p]     * __ldg(wdp + mi * 16);
                s += acc[mi][ni][2 + p] * __ldg(wdp + mi * 16 + 8);
            }
            s += __shfl_xor_sync(0xffffffffu, s, 16);
            s += __shfl_xor_sync(0xffffffffu, s, 8);
            s += __shfl_xor_sync(0xffffffffu, s, 4);
            if (g == 0)
                atomicAdd(&out[(size_t)b * N_DIM + n], s);
        }
    }
}

extern "C" void kernel_launch(void* const* d_in, const int* in_sizes, int n_in,
                              void* d_out, int out_size) {
    const float* x  = (const float*)d_in[0];  // [8192 x 3136]
    const float* Ws = (const float*)d_in[1];  // [1024 x 3136]
    const float* Wd = (const float*)d_in[2];  // [1024 x 256]
    const float* Wb = (const float*)d_in[3];  // [1024]
    float* out = (float*)d_out;               // [32 x 1024] fp32

    static bool attr_set = false;
    if (!attr_set) {
        cudaFuncSetAttribute(gemm_fused,
                             cudaFuncAttributeMaxDynamicSharedMemorySize, SMEM_BYTES);
        attr_set = true;
    }

    prep_all<<<788, 256>>>(Ws, Wb, out);      // Ws->fp16 (MLP=4) + out=W_b
    dim3 grid(8, 64, 4);                      // 2048 CTAs
    gemm_fused<<<grid, 256, SMEM_BYTES>>>(x, Wd, out);
}